// round 2
// baseline (speedup 1.0000x reference)
#include <cuda_runtime.h>
#include <cuda_bf16.h>
#include <cstdint>

// ---------------- problem constants ----------------
#define NN      50000
#define EE      800000
#define IN_DIM  768
#define HID     256
#define OUT_DIM 128
#define BN_EPS  1e-5f
#define NORM_EPS 1e-12f

// ---------------- scratch (device globals — allocation-free) ----------------
__device__ float g_deg[NN];               // degree -> dis (rsqrt) in place
__device__ float g_t[(size_t)NN * HID];   // GEMM output
__device__ float g_a[(size_t)NN * HID];   // aggregation output
__device__ float g_h[(size_t)NN * HID];   // layer input (post BN+ReLU)

// ---------------- helpers ----------------
__device__ __forceinline__ void red_add_v4(float4* p, float4 v) {
    asm volatile("red.global.add.v4.f32 [%0], {%1,%2,%3,%4};"
                 :: "l"(p), "f"(v.x), "f"(v.y), "f"(v.z), "f"(v.w)
                 : "memory");
}

// ---------------- degree / norm ----------------
__global__ void k_deg_init(float* deg, int n) {
    int i = blockIdx.x * blockDim.x + threadIdx.x;
    if (i < n) deg[i] = 1.0f;             // self-loop weight 1
}

__global__ void k_deg_scatter(const int* __restrict__ ei,
                              const float* __restrict__ ew,
                              float* deg, int e) {
    int i = blockIdx.x * blockDim.x + threadIdx.x;
    if (i < e) {
        int d = ei[e + i];                // dst row
        atomicAdd(&deg[d], ew[i]);
    }
}

__global__ void k_rsqrt(float* deg, int n) {
    int i = blockIdx.x * blockDim.x + threadIdx.x;
    if (i < n) {
        float d = deg[i];
        deg[i] = (d > 0.0f) ? rsqrtf(d) : 0.0f;
    }
}

// ---------------- SGEMM: C[M,N] = A[M,K] @ B[K,N] ----------------
// BM=128, BN=128, BK=16, 256 threads, 8x8 per thread.
__global__ __launch_bounds__(256, 2)
void k_sgemm(const float* __restrict__ A, const float* __restrict__ B,
             float* __restrict__ C, int M, int N, int K) {
    __shared__ float As[16][128];
    __shared__ float Bs[16][128];

    const int tid = threadIdx.x;
    const int tx  = tid & 15;        // 0..15
    const int ty  = tid >> 4;        // 0..15
    const int blockRow = blockIdx.y;
    const int blockCol = blockIdx.x;

    const int aRow = tid >> 2;           // 0..63
    const int aCol = (tid & 3) * 4;      // 0,4,8,12
    const int bRow = tid >> 5;           // 0..7
    const int bCol = (tid & 31) * 4;     // 0..124

    const float* Ablk = A + (size_t)blockRow * 128 * K;
    const float* Bblk = B + blockCol * 128;

    float acc[8][8];
#pragma unroll
    for (int i = 0; i < 8; i++)
#pragma unroll
        for (int j = 0; j < 8; j++) acc[i][j] = 0.0f;

    for (int k0 = 0; k0 < K; k0 += 16) {
        // A tile load (transpose into As[k][m])
#pragma unroll
        for (int r = 0; r < 2; r++) {
            int row  = aRow + r * 64;
            int grow = blockRow * 128 + row;
            float4 v = make_float4(0.f, 0.f, 0.f, 0.f);
            if (grow < M)
                v = *(const float4*)(Ablk + (size_t)row * K + k0 + aCol);
            As[aCol + 0][row] = v.x;
            As[aCol + 1][row] = v.y;
            As[aCol + 2][row] = v.z;
            As[aCol + 3][row] = v.w;
        }
        // B tile load
#pragma unroll
        for (int r = 0; r < 2; r++) {
            int row = bRow + r * 8;
            float4 v = *(const float4*)(Bblk + (size_t)(k0 + row) * N + bCol);
            *(float4*)&Bs[row][bCol] = v;
        }
        __syncthreads();

#pragma unroll
        for (int kk = 0; kk < 16; kk++) {
            float4 a0 = *(const float4*)&As[kk][ty * 8];
            float4 a1 = *(const float4*)&As[kk][ty * 8 + 4];
            float4 b0 = *(const float4*)&Bs[kk][tx * 8];
            float4 b1 = *(const float4*)&Bs[kk][tx * 8 + 4];
            float ra[8] = {a0.x, a0.y, a0.z, a0.w, a1.x, a1.y, a1.z, a1.w};
            float rb[8] = {b0.x, b0.y, b0.z, b0.w, b1.x, b1.y, b1.z, b1.w};
#pragma unroll
            for (int i = 0; i < 8; i++)
#pragma unroll
                for (int j = 0; j < 8; j++)
                    acc[i][j] = fmaf(ra[i], rb[j], acc[i][j]);
        }
        __syncthreads();
    }

#pragma unroll
    for (int i = 0; i < 8; i++) {
        int grow = blockRow * 128 + ty * 8 + i;
        if (grow >= M) continue;
        float* Crow = C + (size_t)grow * N + blockCol * 128 + tx * 8;
        *(float4*)(Crow)     = make_float4(acc[i][0], acc[i][1], acc[i][2], acc[i][3]);
        *(float4*)(Crow + 4) = make_float4(acc[i][4], acc[i][5], acc[i][6], acc[i][7]);
    }
}

// ---------------- aggregation init: out = bias + h * dis^2 (self loop) ----------------
template <int F>
__global__ void k_agg_init(const float* __restrict__ hin,
                           const float* __restrict__ bias,
                           const float* __restrict__ dis,
                           float* __restrict__ out, int n) {
    int idx = blockIdx.x * blockDim.x + threadIdx.x;
    const int FC = F / 4;
    if (idx >= n * FC) return;
    int i = idx / FC;
    int c = idx % FC;
    float d = dis[i];
    float d2 = d * d;
    float4 hv = ((const float4*)hin)[idx];
    float4 bv = ((const float4*)bias)[c];
    float4 o;
    o.x = bv.x + hv.x * d2;
    o.y = bv.y + hv.y * d2;
    o.z = bv.z + hv.z * d2;
    o.w = bv.w + hv.w * d2;
    ((float4*)out)[idx] = o;
}

// ---------------- edge scatter: out[dst] += h[src] * norm  (warp per edge) ----------------
template <int F>
__global__ void k_edge_scatter(const int* __restrict__ ei,
                               const float* __restrict__ ew,
                               const float* __restrict__ dis,
                               const float* __restrict__ hin,
                               float* __restrict__ out, int e) {
    int eidx = blockIdx.x * 8 + (threadIdx.x >> 5);
    if (eidx >= e) return;
    int lane = threadIdx.x & 31;
    int s = ei[eidx];
    int d = ei[e + eidx];
    float nrm = dis[s] * ew[eidx] * dis[d];
    const float4* srcp = (const float4*)(hin + (size_t)s * F);
    float4* dstp = (float4*)(out + (size_t)d * F);
#pragma unroll
    for (int j = 0; j < F / 128; j++) {
        float4 v = srcp[lane + j * 32];
        v.x *= nrm; v.y *= nrm; v.z *= nrm; v.w *= nrm;
        red_add_v4(&dstp[lane + j * 32], v);
    }
}

// ---------------- BN (eval) + ReLU ----------------
template <int F>
__global__ void k_bn_relu(const float* __restrict__ in,
                          const float* __restrict__ gamma,
                          const float* __restrict__ beta,
                          const float* __restrict__ mean,
                          const float* __restrict__ var,
                          float* __restrict__ out, int n) {
    int idx = blockIdx.x * blockDim.x + threadIdx.x;
    const int FC = F / 4;
    if (idx >= n * FC) return;
    int c = idx % FC;
    float4 g = ((const float4*)gamma)[c];
    float4 b = ((const float4*)beta)[c];
    float4 m = ((const float4*)mean)[c];
    float4 v = ((const float4*)var)[c];
    float4 h = ((const float4*)in)[idx];
    float4 o;
    o.x = fmaxf((h.x - m.x) * rsqrtf(v.x + BN_EPS) * g.x + b.x, 0.0f);
    o.y = fmaxf((h.y - m.y) * rsqrtf(v.y + BN_EPS) * g.y + b.y, 0.0f);
    o.z = fmaxf((h.z - m.z) * rsqrtf(v.z + BN_EPS) * g.z + b.z, 0.0f);
    o.w = fmaxf((h.w - m.w) * rsqrtf(v.w + BN_EPS) * g.w + b.w, 0.0f);
    ((float4*)out)[idx] = o;
}

// ---------------- row L2 normalize (warp per row, F=128) ----------------
__global__ void k_l2norm(const float* __restrict__ in, float* __restrict__ out, int n) {
    int row = blockIdx.x * 8 + (threadIdx.x >> 5);
    if (row >= n) return;
    int lane = threadIdx.x & 31;
    const float4* rp = (const float4*)(in + (size_t)row * OUT_DIM);
    float4 v = rp[lane];
    float ss = v.x * v.x + v.y * v.y + v.z * v.z + v.w * v.w;
#pragma unroll
    for (int o = 16; o > 0; o >>= 1)
        ss += __shfl_xor_sync(0xFFFFFFFFu, ss, o);
    float nrm = sqrtf(ss);
    float inv = 1.0f / fmaxf(nrm, NORM_EPS);
    float4 o4;
    o4.x = v.x * inv; o4.y = v.y * inv; o4.z = v.z * inv; o4.w = v.w * inv;
    ((float4*)(out + (size_t)row * OUT_DIM))[lane] = o4;
}

// ---------------- launch ----------------
extern "C" void kernel_launch(void* const* d_in, const int* in_sizes, int n_in,
                              void* d_out, int out_size) {
    const float* x   = (const float*)d_in[0];
    const int*   ei  = (const int*)d_in[1];     // JAX x64 disabled: int32
    const float* ew  = (const float*)d_in[2];
    const float* W1  = (const float*)d_in[3];
    const float* b1  = (const float*)d_in[4];
    const float* W2  = (const float*)d_in[5];
    const float* b2  = (const float*)d_in[6];
    const float* W3  = (const float*)d_in[7];
    const float* b3  = (const float*)d_in[8];
    const float* bn1_g = (const float*)d_in[9];
    const float* bn1_b = (const float*)d_in[10];
    const float* bn1_m = (const float*)d_in[11];
    const float* bn1_v = (const float*)d_in[12];
    const float* bn2_g = (const float*)d_in[13];
    const float* bn2_b = (const float*)d_in[14];
    const float* bn2_m = (const float*)d_in[15];
    const float* bn2_v = (const float*)d_in[16];
    float* out = (float*)d_out;

    const int n = NN;
    const int e = in_sizes[2];   // 800000

    float *deg, *t, *a, *h;
    cudaGetSymbolAddress((void**)&deg, g_deg);
    cudaGetSymbolAddress((void**)&t,   g_t);
    cudaGetSymbolAddress((void**)&a,   g_a);
    cudaGetSymbolAddress((void**)&h,   g_h);

    const int TB = 256;
    // degree -> dis
    k_deg_init<<<(n + TB - 1) / TB, TB>>>(deg, n);
    k_deg_scatter<<<(e + TB - 1) / TB, TB>>>(ei, ew, deg, e);
    k_rsqrt<<<(n + TB - 1) / TB, TB>>>(deg, n);

    dim3 gemm_block(256);
    int mBlocks = (n + 127) / 128;
    int eBlocks = (e + 7) / 8;
    int nv256 = n * (HID / 4);
    int nv128 = n * (OUT_DIM / 4);

    // ---- layer 1: x@W1 -> aggregate -> bn1+relu ----
    {
        dim3 grid(HID / 128, mBlocks);
        k_sgemm<<<grid, gemm_block>>>(x, W1, t, n, HID, IN_DIM);
    }
    k_agg_init<HID><<<(nv256 + TB - 1) / TB, TB>>>(t, b1, deg, a, n);
    k_edge_scatter<HID><<<eBlocks, 256>>>(ei, ew, deg, t, a, e);
    k_bn_relu<HID><<<(nv256 + TB - 1) / TB, TB>>>(a, bn1_g, bn1_b, bn1_m, bn1_v, h, n);

    // ---- layer 2: h@W2 -> aggregate -> bn2+relu ----
    {
        dim3 grid(HID / 128, mBlocks);
        k_sgemm<<<grid, gemm_block>>>(h, W2, t, n, HID, HID);
    }
    k_agg_init<HID><<<(nv256 + TB - 1) / TB, TB>>>(t, b2, deg, a, n);
    k_edge_scatter<HID><<<eBlocks, 256>>>(ei, ew, deg, t, a, e);
    k_bn_relu<HID><<<(nv256 + TB - 1) / TB, TB>>>(a, bn2_g, bn2_b, bn2_m, bn2_v, h, n);

    // ---- layer 3: h@W3 -> aggregate -> l2 normalize ----
    {
        dim3 grid(OUT_DIM / 128, mBlocks);
        k_sgemm<<<grid, gemm_block>>>(h, W3, t, n, OUT_DIM, HID);
    }
    k_agg_init<OUT_DIM><<<(nv128 + TB - 1) / TB, TB>>>(t, b3, deg, a, n);
    k_edge_scatter<OUT_DIM><<<eBlocks, 256>>>(ei, ew, deg, t, a, e);
    k_l2norm<<<(n + 7) / 8, 256>>>(a, out, n);
}

// round 3
// speedup vs baseline: 1.0948x; 1.0948x over previous
#include <cuda_runtime.h>
#include <cuda_bf16.h>
#include <cstdint>

// ---------------- problem constants ----------------
#define NN      50000
#define EE      800000
#define IN_DIM  768
#define HID     256
#define OUT_DIM 128
#define BN_EPS  1e-5f
#define NORM_EPS 1e-12f

// ---------------- scratch (device globals — allocation-free) ----------------
__device__ float g_deg[NN];               // degree -> dis (rsqrt) in place
__device__ float g_t[(size_t)NN * HID];   // GEMM output (gather source)
__device__ float g_a[(size_t)NN * HID];   // aggregation output
__device__ float g_h[(size_t)NN * HID];   // layer input (post BN+ReLU)

// ---------------- helpers ----------------
__device__ __forceinline__ void red_add_v4(float4* p, float4 v) {
    asm volatile("red.global.add.v4.f32 [%0], {%1,%2,%3,%4};"
                 :: "l"(p), "f"(v.x), "f"(v.y), "f"(v.z), "f"(v.w)
                 : "memory");
}

__device__ __forceinline__ uint32_t smem_u32(const void* p) {
    uint32_t a;
    asm("{ .reg .u64 t; cvta.to.shared.u64 t, %1; cvt.u32.u64 %0, t; }"
        : "=r"(a) : "l"(p));
    return a;
}

__device__ __forceinline__ void cp_async16(uint32_t smem, const void* g) {
    asm volatile("cp.async.cg.shared.global [%0], [%1], 16;"
                 :: "r"(smem), "l"(g) : "memory");
}
#define CP_COMMIT() asm volatile("cp.async.commit_group;" ::: "memory")
#define CP_WAIT0()  asm volatile("cp.async.wait_group 0;" ::: "memory")

// ---------------- degree / norm ----------------
__global__ void k_deg_init(float* deg, int n) {
    int i = blockIdx.x * blockDim.x + threadIdx.x;
    if (i < n) deg[i] = 1.0f;             // self-loop weight 1
}

__global__ void k_deg_scatter(const int* __restrict__ ei,
                              const float* __restrict__ ew,
                              float* deg, int e) {
    int i = blockIdx.x * blockDim.x + threadIdx.x;
    if (i < e) {
        int d = ei[e + i];                // dst row
        atomicAdd(&deg[d], ew[i]);
    }
}

__global__ void k_rsqrt(float* deg, int n) {
    int i = blockIdx.x * blockDim.x + threadIdx.x;
    if (i < n) {
        float d = deg[i];
        deg[i] = (d > 0.0f) ? rsqrtf(d) : 0.0f;
    }
}

// ---------------- SGEMM fused with agg-init epilogue ----------------
// C[M,N] = A[M,K] @ B[K,N];  Cagg = bias + C * dis[row]^2
// BM=128, BN=128, BK=16, 256 threads, 8x8/thread, 2-stage pipeline:
//   B tiles via cp.async, A tiles register-staged (transposed into smem).
__global__ __launch_bounds__(256, 2)
void k_sgemm_fused(const float* __restrict__ A, const float* __restrict__ B,
                   float* __restrict__ C, float* __restrict__ Cagg,
                   const float* __restrict__ bias, const float* __restrict__ dis,
                   int M, int N, int K) {
    __shared__ float As[2][16][128];
    __shared__ float Bs[2][16][128];

    const int tid = threadIdx.x;
    const int tx  = tid & 15;        // 0..15
    const int ty  = tid >> 4;        // 0..15
    const int blockRow = blockIdx.y;
    const int blockCol = blockIdx.x;

    const int aRow = tid >> 2;           // 0..63
    const int aCol = (tid & 3) * 4;      // 0,4,8,12
    const int bRow = tid >> 5;           // 0..7
    const int bCol = (tid & 31) * 4;     // 0..124

    const float* Ablk = A + (size_t)blockRow * 128 * K;
    const float* Bblk = B + blockCol * 128;

    float acc[8][8];
#pragma unroll
    for (int i = 0; i < 8; i++)
#pragma unroll
        for (int j = 0; j < 8; j++) acc[i][j] = 0.0f;

    float4 ra[2];

    // ---- prologue: stage tile k0=0 into buffer 0 ----
#pragma unroll
    for (int r = 0; r < 2; r++) {
        int row  = aRow + r * 64;
        int grow = blockRow * 128 + row;
        ra[r] = make_float4(0.f, 0.f, 0.f, 0.f);
        if (grow < M)
            ra[r] = *(const float4*)(Ablk + (size_t)row * K + aCol);
    }
#pragma unroll
    for (int r = 0; r < 2; r++) {
        int row = bRow + r * 8;
        cp_async16(smem_u32(&Bs[0][row][bCol]),
                   Bblk + (size_t)row * N + bCol);
    }
    CP_COMMIT();
#pragma unroll
    for (int r = 0; r < 2; r++) {
        int row = aRow + r * 64;
        As[0][aCol + 0][row] = ra[r].x;
        As[0][aCol + 1][row] = ra[r].y;
        As[0][aCol + 2][row] = ra[r].z;
        As[0][aCol + 3][row] = ra[r].w;
    }
    CP_WAIT0();
    __syncthreads();

    int buf = 0;
    for (int k0 = 16; k0 < K; k0 += 16) {
        int nbuf = buf ^ 1;
        // prefetch B (cp.async) and A (registers) for next tile
#pragma unroll
        for (int r = 0; r < 2; r++) {
            int row = bRow + r * 8;
            cp_async16(smem_u32(&Bs[nbuf][row][bCol]),
                       Bblk + (size_t)(k0 + row) * N + bCol);
        }
        CP_COMMIT();
#pragma unroll
        for (int r = 0; r < 2; r++) {
            int row  = aRow + r * 64;
            int grow = blockRow * 128 + row;
            ra[r] = make_float4(0.f, 0.f, 0.f, 0.f);
            if (grow < M)
                ra[r] = *(const float4*)(Ablk + (size_t)row * K + k0 + aCol);
        }

        // compute current tile
#pragma unroll
        for (int kk = 0; kk < 16; kk++) {
            float4 a0 = *(const float4*)&As[buf][kk][ty * 8];
            float4 a1 = *(const float4*)&As[buf][kk][ty * 8 + 4];
            float4 b0 = *(const float4*)&Bs[buf][kk][tx * 8];
            float4 b1 = *(const float4*)&Bs[buf][kk][tx * 8 + 4];
            float fa[8] = {a0.x, a0.y, a0.z, a0.w, a1.x, a1.y, a1.z, a1.w};
            float fb[8] = {b0.x, b0.y, b0.z, b0.w, b1.x, b1.y, b1.z, b1.w};
#pragma unroll
            for (int i = 0; i < 8; i++)
#pragma unroll
                for (int j = 0; j < 8; j++)
                    acc[i][j] = fmaf(fa[i], fb[j], acc[i][j]);
        }

        // stage A into next buffer
#pragma unroll
        for (int r = 0; r < 2; r++) {
            int row = aRow + r * 64;
            As[nbuf][aCol + 0][row] = ra[r].x;
            As[nbuf][aCol + 1][row] = ra[r].y;
            As[nbuf][aCol + 2][row] = ra[r].z;
            As[nbuf][aCol + 3][row] = ra[r].w;
        }
        CP_WAIT0();
        __syncthreads();
        buf = nbuf;
    }

    // final tile
#pragma unroll
    for (int kk = 0; kk < 16; kk++) {
        float4 a0 = *(const float4*)&As[buf][kk][ty * 8];
        float4 a1 = *(const float4*)&As[buf][kk][ty * 8 + 4];
        float4 b0 = *(const float4*)&Bs[buf][kk][tx * 8];
        float4 b1 = *(const float4*)&Bs[buf][kk][tx * 8 + 4];
        float fa[8] = {a0.x, a0.y, a0.z, a0.w, a1.x, a1.y, a1.z, a1.w};
        float fb[8] = {b0.x, b0.y, b0.z, b0.w, b1.x, b1.y, b1.z, b1.w};
#pragma unroll
        for (int i = 0; i < 8; i++)
#pragma unroll
            for (int j = 0; j < 8; j++)
                acc[i][j] = fmaf(fa[i], fb[j], acc[i][j]);
    }

    // ---- epilogue: write C and Cagg = bias + C*dis^2 ----
    int colBase = blockCol * 128 + tx * 8;
    float4 bv0 = *(const float4*)(bias + colBase);
    float4 bv1 = *(const float4*)(bias + colBase + 4);
#pragma unroll
    for (int i = 0; i < 8; i++) {
        int grow = blockRow * 128 + ty * 8 + i;
        if (grow >= M) continue;
        float dv = dis[grow];
        float d2 = dv * dv;
        size_t off = (size_t)grow * N + colBase;
        float4 c0 = make_float4(acc[i][0], acc[i][1], acc[i][2], acc[i][3]);
        float4 c1 = make_float4(acc[i][4], acc[i][5], acc[i][6], acc[i][7]);
        *(float4*)(C + off)     = c0;
        *(float4*)(C + off + 4) = c1;
        float4 g0, g1;
        g0.x = bv0.x + c0.x * d2; g0.y = bv0.y + c0.y * d2;
        g0.z = bv0.z + c0.z * d2; g0.w = bv0.w + c0.w * d2;
        g1.x = bv1.x + c1.x * d2; g1.y = bv1.y + c1.y * d2;
        g1.z = bv1.z + c1.z * d2; g1.w = bv1.w + c1.w * d2;
        *(float4*)(Cagg + off)     = g0;
        *(float4*)(Cagg + off + 4) = g1;
    }
}

// ---------------- edge scatter: out[dst] += h[src] * norm  (warp per edge) ----------------
template <int F>
__global__ void k_edge_scatter(const int* __restrict__ ei,
                               const float* __restrict__ ew,
                               const float* __restrict__ dis,
                               const float* __restrict__ hin,
                               float* __restrict__ out, int e) {
    int eidx = blockIdx.x * 8 + (threadIdx.x >> 5);
    if (eidx >= e) return;
    int lane = threadIdx.x & 31;
    int s = ei[eidx];
    int d = ei[e + eidx];
    float nrm = dis[s] * ew[eidx] * dis[d];
    const float4* srcp = (const float4*)(hin + (size_t)s * F);
    float4* dstp = (float4*)(out + (size_t)d * F);
#pragma unroll
    for (int j = 0; j < F / 128; j++) {
        float4 v = srcp[lane + j * 32];
        v.x *= nrm; v.y *= nrm; v.z *= nrm; v.w *= nrm;
        red_add_v4(&dstp[lane + j * 32], v);
    }
}

// ---------------- BN (eval) + ReLU ----------------
template <int F>
__global__ void k_bn_relu(const float* __restrict__ in,
                          const float* __restrict__ gamma,
                          const float* __restrict__ beta,
                          const float* __restrict__ mean,
                          const float* __restrict__ var,
                          float* __restrict__ out, int n) {
    int idx = blockIdx.x * blockDim.x + threadIdx.x;
    const int FC = F / 4;
    if (idx >= n * FC) return;
    int c = idx % FC;
    float4 g = ((const float4*)gamma)[c];
    float4 b = ((const float4*)beta)[c];
    float4 m = ((const float4*)mean)[c];
    float4 v = ((const float4*)var)[c];
    float4 h = ((const float4*)in)[idx];
    float4 o;
    o.x = fmaxf((h.x - m.x) * rsqrtf(v.x + BN_EPS) * g.x + b.x, 0.0f);
    o.y = fmaxf((h.y - m.y) * rsqrtf(v.y + BN_EPS) * g.y + b.y, 0.0f);
    o.z = fmaxf((h.z - m.z) * rsqrtf(v.z + BN_EPS) * g.z + b.z, 0.0f);
    o.w = fmaxf((h.w - m.w) * rsqrtf(v.w + BN_EPS) * g.w + b.w, 0.0f);
    ((float4*)out)[idx] = o;
}

// ---------------- row L2 normalize (warp per row, F=128) ----------------
__global__ void k_l2norm(const float* __restrict__ in, float* __restrict__ out, int n) {
    int row = blockIdx.x * 8 + (threadIdx.x >> 5);
    if (row >= n) return;
    int lane = threadIdx.x & 31;
    const float4* rp = (const float4*)(in + (size_t)row * OUT_DIM);
    float4 v = rp[lane];
    float ss = v.x * v.x + v.y * v.y + v.z * v.z + v.w * v.w;
#pragma unroll
    for (int o = 16; o > 0; o >>= 1)
        ss += __shfl_xor_sync(0xFFFFFFFFu, ss, o);
    float nrm = sqrtf(ss);
    float inv = 1.0f / fmaxf(nrm, NORM_EPS);
    float4 o4;
    o4.x = v.x * inv; o4.y = v.y * inv; o4.z = v.z * inv; o4.w = v.w * inv;
    ((float4*)(out + (size_t)row * OUT_DIM))[lane] = o4;
}

// ---------------- launch ----------------
extern "C" void kernel_launch(void* const* d_in, const int* in_sizes, int n_in,
                              void* d_out, int out_size) {
    const float* x   = (const float*)d_in[0];
    const int*   ei  = (const int*)d_in[1];     // int32 (JAX x64 disabled)
    const float* ew  = (const float*)d_in[2];
    const float* W1  = (const float*)d_in[3];
    const float* b1  = (const float*)d_in[4];
    const float* W2  = (const float*)d_in[5];
    const float* b2  = (const float*)d_in[6];
    const float* W3  = (const float*)d_in[7];
    const float* b3  = (const float*)d_in[8];
    const float* bn1_g = (const float*)d_in[9];
    const float* bn1_b = (const float*)d_in[10];
    const float* bn1_m = (const float*)d_in[11];
    const float* bn1_v = (const float*)d_in[12];
    const float* bn2_g = (const float*)d_in[13];
    const float* bn2_b = (const float*)d_in[14];
    const float* bn2_m = (const float*)d_in[15];
    const float* bn2_v = (const float*)d_in[16];
    float* out = (float*)d_out;

    const int n = NN;
    const int e = in_sizes[2];   // 800000

    float *deg, *t, *a, *h;
    cudaGetSymbolAddress((void**)&deg, g_deg);
    cudaGetSymbolAddress((void**)&t,   g_t);
    cudaGetSymbolAddress((void**)&a,   g_a);
    cudaGetSymbolAddress((void**)&h,   g_h);

    const int TB = 256;
    // degree -> dis
    k_deg_init<<<(n + TB - 1) / TB, TB>>>(deg, n);
    k_deg_scatter<<<(e + TB - 1) / TB, TB>>>(ei, ew, deg, e);
    k_rsqrt<<<(n + TB - 1) / TB, TB>>>(deg, n);

    dim3 gemm_block(256);
    int mBlocks = (n + 127) / 128;
    int eBlocks = (e + 7) / 8;
    int nv256 = n * (HID / 4);

    // ---- layer 1: x@W1 (+agg init) -> scatter -> bn1+relu ----
    {
        dim3 grid(HID / 128, mBlocks);
        k_sgemm_fused<<<grid, gemm_block>>>(x, W1, t, a, b1, deg, n, HID, IN_DIM);
    }
    k_edge_scatter<HID><<<eBlocks, 256>>>(ei, ew, deg, t, a, e);
    k_bn_relu<HID><<<(nv256 + TB - 1) / TB, TB>>>(a, bn1_g, bn1_b, bn1_m, bn1_v, h, n);

    // ---- layer 2 ----
    {
        dim3 grid(HID / 128, mBlocks);
        k_sgemm_fused<<<grid, gemm_block>>>(h, W2, t, a, b2, deg, n, HID, HID);
    }
    k_edge_scatter<HID><<<eBlocks, 256>>>(ei, ew, deg, t, a, e);
    k_bn_relu<HID><<<(nv256 + TB - 1) / TB, TB>>>(a, bn2_g, bn2_b, bn2_m, bn2_v, h, n);

    // ---- layer 3 ----
    {
        dim3 grid(OUT_DIM / 128, mBlocks);
        k_sgemm_fused<<<grid, gemm_block>>>(h, W3, t, a, b3, deg, n, OUT_DIM, HID);
    }
    k_edge_scatter<OUT_DIM><<<eBlocks, 256>>>(ei, ew, deg, t, a, e);
    k_l2norm<<<(n + 7) / 8, 256>>>(a, out, n);
}